// round 12
// baseline (speedup 1.0000x reference)
#include <cuda_runtime.h>
#include <math.h>

#define BB    16
#define NN    4096
#define KSEL  17           // K+1 (includes self at distance 0)
#define TPB   128
#define ALPHA 1.05f

// Scratch (no allocations allowed): per-point mean kNN distance + per-batch penalty sums
__device__ float g_knnd[BB * NN];
__device__ float g_partial[BB];

// ---------------------------------------------------------------------------
// Stage 1: brute-force kNN per point. One thread = one query point.
// Whole batch tile (4096 pts, SoA) lives in static smem; candidate loads are
// warp-broadcast LDS. Top-17 kept in a sorted-descending register array;
// insert is a compare-free merge network (2 FMNMX per slot).
// ---------------------------------------------------------------------------
__global__ __launch_bounds__(TPB) void knn_stage1(const float* __restrict__ pcs) {
    __shared__ float sx[NN];
    __shared__ float sy[NN];
    __shared__ float sz[NN];

    const int b = blockIdx.y;
    const float* base = pcs + (size_t)b * NN * 3;

    for (int t = threadIdx.x; t < NN; t += TPB) {
        sx[t] = base[3 * t + 0];
        sy[t] = base[3 * t + 1];
        sz[t] = base[3 * t + 2];
    }
    __syncthreads();

    const int i = blockIdx.x * TPB + threadIdx.x;
    const float qx = sx[i], qy = sy[i], qz = sz[i];

    // arr sorted descending; arr[0] = current worst of the kept 17
    float arr[KSEL];
    const float INF = __int_as_float(0x7f800000);
#pragma unroll
    for (int k = 0; k < KSEL; k++) arr[k] = INF;

#pragma unroll 4
    for (int j = 0; j < NN; j++) {
        float dx = qx - sx[j];
        float dy = qy - sy[j];
        float dz = qz - sz[j];
        float d  = fmaf(dx, dx, fmaf(dy, dy, dz * dz));
        if (d < arr[0]) {
            // merge-insert: drop arr[0] (old max), place d in sorted position
#pragma unroll
            for (int k = 0; k < KSEL - 1; k++)
                arr[k] = fmaxf(arr[k + 1], fminf(arr[k], d));
            arr[KSEL - 1] = fminf(arr[KSEL - 1], d);
        }
    }

    // arr[16] is the minimum = self distance (exactly 0). Mean of the other 16.
    float s = 0.0f;
#pragma unroll
    for (int k = 0; k < KSEL - 1; k++) s += arr[k];
    g_knnd[b * NN + i] = s * (1.0f / 16.0f);
}

// ---------------------------------------------------------------------------
// Stage 2: per-batch mean, population std (two-pass, matches jnp.std), then
// outlier penalty sum. One block per batch; values held in registers across
// the three deterministic tree reductions.
// ---------------------------------------------------------------------------
__global__ __launch_bounds__(256) void knn_stage2() {
    const int b   = blockIdx.x;
    const int tid = threadIdx.x;
    const int PER = NN / 256; // 16

    float v[PER];
    float s = 0.0f;
#pragma unroll
    for (int r = 0; r < PER; r++) {
        v[r] = g_knnd[b * NN + r * 256 + tid];
        s += v[r];
    }

    __shared__ float red[256];
    __shared__ float mu_s, sig_s;

    // sum -> mu
    red[tid] = s;
    __syncthreads();
    for (int off = 128; off > 0; off >>= 1) {
        if (tid < off) red[tid] += red[tid + off];
        __syncthreads();
    }
    if (tid == 0) mu_s = red[0] * (1.0f / NN);
    __syncthreads();
    const float mu = mu_s;

    // sum (x-mu)^2 -> sigma
    float vs = 0.0f;
#pragma unroll
    for (int r = 0; r < PER; r++) {
        float d = v[r] - mu;
        vs = fmaf(d, d, vs);
    }
    red[tid] = vs;
    __syncthreads();
    for (int off = 128; off > 0; off >>= 1) {
        if (tid < off) red[tid] += red[tid + off];
        __syncthreads();
    }
    if (tid == 0) sig_s = sqrtf(red[0] * (1.0f / NN));
    __syncthreads();

    const float thresh = mu + ALPHA * sig_s;

    // penalty sum for this batch
    float ps = 0.0f;
#pragma unroll
    for (int r = 0; r < PER; r++)
        if (v[r] > thresh) ps += v[r];
    red[tid] = ps;
    __syncthreads();
    for (int off = 128; off > 0; off >>= 1) {
        if (tid < off) red[tid] += red[tid + off];
        __syncthreads();
    }
    if (tid == 0) g_partial[b] = red[0];
}

// ---------------------------------------------------------------------------
// Stage 3: fold 16 batch partials into the scalar output (deterministic).
// ---------------------------------------------------------------------------
__global__ void knn_stage3(float* __restrict__ out) {
    float s = 0.0f;
#pragma unroll
    for (int b = 0; b < BB; b++) s += g_partial[b];
    out[0] = s * (1.0f / ((float)BB * (float)NN));
}

extern "C" void kernel_launch(void* const* d_in, const int* in_sizes, int n_in,
                              void* d_out, int out_size) {
    const float* pcs = (const float*)d_in[0];
    (void)in_sizes; (void)n_in; (void)out_size;

    dim3 grid1(NN / TPB, BB);
    knn_stage1<<<grid1, TPB>>>(pcs);
    knn_stage2<<<BB, 256>>>();
    knn_stage3<<<1, 1>>>((float*)d_out);
}

// round 13
// speedup vs baseline: 1.0003x; 1.0003x over previous
#include <cuda_runtime.h>
#include <math.h>

#define BB    16
#define NN    4096
#define KSEL  17           // K+1 (includes self at distance 0)
#define TPB   128
#define ALPHA 1.05f

// Scratch (no allocations allowed): per-point mean kNN distance + per-batch penalty sums
__device__ float g_knnd[BB * NN];
__device__ float g_partial[BB];

// ---------------------------------------------------------------------------
// Stage 1: brute-force kNN per point. One thread = one query point.
// Whole batch tile (4096 pts, SoA) lives in static smem; candidate loads are
// warp-broadcast LDS. Top-17 kept in a sorted-descending register array;
// insert is a compare-free merge network (2 FMNMX per slot).
// ---------------------------------------------------------------------------
__global__ __launch_bounds__(TPB) void knn_stage1(const float* __restrict__ pcs) {
    __shared__ float sx[NN];
    __shared__ float sy[NN];
    __shared__ float sz[NN];

    const int b = blockIdx.y;
    const float* base = pcs + (size_t)b * NN * 3;

    for (int t = threadIdx.x; t < NN; t += TPB) {
        sx[t] = base[3 * t + 0];
        sy[t] = base[3 * t + 1];
        sz[t] = base[3 * t + 2];
    }
    __syncthreads();

    const int i = blockIdx.x * TPB + threadIdx.x;
    const float qx = sx[i], qy = sy[i], qz = sz[i];

    // arr sorted descending; arr[0] = current worst of the kept 17
    float arr[KSEL];
    const float INF = __int_as_float(0x7f800000);
#pragma unroll
    for (int k = 0; k < KSEL; k++) arr[k] = INF;

#pragma unroll 4
    for (int j = 0; j < NN; j++) {
        float dx = qx - sx[j];
        float dy = qy - sy[j];
        float dz = qz - sz[j];
        float d  = fmaf(dx, dx, fmaf(dy, dy, dz * dz));
        if (d < arr[0]) {
            // merge-insert: drop arr[0] (old max), place d in sorted position
#pragma unroll
            for (int k = 0; k < KSEL - 1; k++)
                arr[k] = fmaxf(arr[k + 1], fminf(arr[k], d));
            arr[KSEL - 1] = fminf(arr[KSEL - 1], d);
        }
    }

    // arr[16] is the minimum = self distance (exactly 0). Mean of the other 16.
    float s = 0.0f;
#pragma unroll
    for (int k = 0; k < KSEL - 1; k++) s += arr[k];
    g_knnd[b * NN + i] = s * (1.0f / 16.0f);
}

// ---------------------------------------------------------------------------
// Stage 2: per-batch mean, population std (two-pass, matches jnp.std), then
// outlier penalty sum. One block per batch; values held in registers across
// the three deterministic tree reductions.
// ---------------------------------------------------------------------------
__global__ __launch_bounds__(256) void knn_stage2() {
    const int b   = blockIdx.x;
    const int tid = threadIdx.x;
    const int PER = NN / 256; // 16

    float v[PER];
    float s = 0.0f;
#pragma unroll
    for (int r = 0; r < PER; r++) {
        v[r] = g_knnd[b * NN + r * 256 + tid];
        s += v[r];
    }

    __shared__ float red[256];
    __shared__ float mu_s, sig_s;

    // sum -> mu
    red[tid] = s;
    __syncthreads();
    for (int off = 128; off > 0; off >>= 1) {
        if (tid < off) red[tid] += red[tid + off];
        __syncthreads();
    }
    if (tid == 0) mu_s = red[0] * (1.0f / NN);
    __syncthreads();
    const float mu = mu_s;

    // sum (x-mu)^2 -> sigma
    float vs = 0.0f;
#pragma unroll
    for (int r = 0; r < PER; r++) {
        float d = v[r] - mu;
        vs = fmaf(d, d, vs);
    }
    red[tid] = vs;
    __syncthreads();
    for (int off = 128; off > 0; off >>= 1) {
        if (tid < off) red[tid] += red[tid + off];
        __syncthreads();
    }
    if (tid == 0) sig_s = sqrtf(red[0] * (1.0f / NN));
    __syncthreads();

    const float thresh = mu + ALPHA * sig_s;

    // penalty sum for this batch
    float ps = 0.0f;
#pragma unroll
    for (int r = 0; r < PER; r++)
        if (v[r] > thresh) ps += v[r];
    red[tid] = ps;
    __syncthreads();
    for (int off = 128; off > 0; off >>= 1) {
        if (tid < off) red[tid] += red[tid + off];
        __syncthreads();
    }
    if (tid == 0) g_partial[b] = red[0];
}

// ---------------------------------------------------------------------------
// Stage 3: fold 16 batch partials into the scalar output (deterministic).
// ---------------------------------------------------------------------------
__global__ void knn_stage3(float* __restrict__ out) {
    float s = 0.0f;
#pragma unroll
    for (int b = 0; b < BB; b++) s += g_partial[b];
    out[0] = s * (1.0f / ((float)BB * (float)NN));
}

extern "C" void kernel_launch(void* const* d_in, const int* in_sizes, int n_in,
                              void* d_out, int out_size) {
    const float* pcs = (const float*)d_in[0];
    (void)in_sizes; (void)n_in; (void)out_size;

    dim3 grid1(NN / TPB, BB);
    knn_stage1<<<grid1, TPB>>>(pcs);
    knn_stage2<<<BB, 256>>>();
    knn_stage3<<<1, 1>>>((float*)d_out);
}

// round 14
// speedup vs baseline: 1.0011x; 1.0009x over previous
#include <cuda_runtime.h>
#include <math.h>

#define BB    16
#define NN    4096
#define KSEL  17           // K+1 (includes self at distance 0)
#define TPB   128
#define ALPHA 1.05f

// Scratch (no allocations allowed): per-point mean kNN distance + per-batch penalty sums
__device__ float g_knnd[BB * NN];
__device__ float g_partial[BB];

// ---------------------------------------------------------------------------
// Stage 1: brute-force kNN per point. One thread = one query point.
// Whole batch tile (4096 pts, SoA) lives in static smem; candidate loads are
// warp-broadcast LDS. Top-17 kept in a sorted-descending register array;
// insert is a compare-free merge network (2 FMNMX per slot).
// ---------------------------------------------------------------------------
__global__ __launch_bounds__(TPB) void knn_stage1(const float* __restrict__ pcs) {
    __shared__ float sx[NN];
    __shared__ float sy[NN];
    __shared__ float sz[NN];

    const int b = blockIdx.y;
    const float* base = pcs + (size_t)b * NN * 3;

    for (int t = threadIdx.x; t < NN; t += TPB) {
        sx[t] = base[3 * t + 0];
        sy[t] = base[3 * t + 1];
        sz[t] = base[3 * t + 2];
    }
    __syncthreads();

    const int i = blockIdx.x * TPB + threadIdx.x;
    const float qx = sx[i], qy = sy[i], qz = sz[i];

    // arr sorted descending; arr[0] = current worst of the kept 17
    float arr[KSEL];
    const float INF = __int_as_float(0x7f800000);
#pragma unroll
    for (int k = 0; k < KSEL; k++) arr[k] = INF;

#pragma unroll 4
    for (int j = 0; j < NN; j++) {
        float dx = qx - sx[j];
        float dy = qy - sy[j];
        float dz = qz - sz[j];
        float d  = fmaf(dx, dx, fmaf(dy, dy, dz * dz));
        if (d < arr[0]) {
            // merge-insert: drop arr[0] (old max), place d in sorted position
#pragma unroll
            for (int k = 0; k < KSEL - 1; k++)
                arr[k] = fmaxf(arr[k + 1], fminf(arr[k], d));
            arr[KSEL - 1] = fminf(arr[KSEL - 1], d);
        }
    }

    // arr[16] is the minimum = self distance (exactly 0). Mean of the other 16.
    float s = 0.0f;
#pragma unroll
    for (int k = 0; k < KSEL - 1; k++) s += arr[k];
    g_knnd[b * NN + i] = s * (1.0f / 16.0f);
}

// ---------------------------------------------------------------------------
// Stage 2: per-batch mean, population std (two-pass, matches jnp.std), then
// outlier penalty sum. One block per batch; values held in registers across
// the three deterministic tree reductions.
// ---------------------------------------------------------------------------
__global__ __launch_bounds__(256) void knn_stage2() {
    const int b   = blockIdx.x;
    const int tid = threadIdx.x;
    const int PER = NN / 256; // 16

    float v[PER];
    float s = 0.0f;
#pragma unroll
    for (int r = 0; r < PER; r++) {
        v[r] = g_knnd[b * NN + r * 256 + tid];
        s += v[r];
    }

    __shared__ float red[256];
    __shared__ float mu_s, sig_s;

    // sum -> mu
    red[tid] = s;
    __syncthreads();
    for (int off = 128; off > 0; off >>= 1) {
        if (tid < off) red[tid] += red[tid + off];
        __syncthreads();
    }
    if (tid == 0) mu_s = red[0] * (1.0f / NN);
    __syncthreads();
    const float mu = mu_s;

    // sum (x-mu)^2 -> sigma
    float vs = 0.0f;
#pragma unroll
    for (int r = 0; r < PER; r++) {
        float d = v[r] - mu;
        vs = fmaf(d, d, vs);
    }
    red[tid] = vs;
    __syncthreads();
    for (int off = 128; off > 0; off >>= 1) {
        if (tid < off) red[tid] += red[tid + off];
        __syncthreads();
    }
    if (tid == 0) sig_s = sqrtf(red[0] * (1.0f / NN));
    __syncthreads();

    const float thresh = mu + ALPHA * sig_s;

    // penalty sum for this batch
    float ps = 0.0f;
#pragma unroll
    for (int r = 0; r < PER; r++)
        if (v[r] > thresh) ps += v[r];
    red[tid] = ps;
    __syncthreads();
    for (int off = 128; off > 0; off >>= 1) {
        if (tid < off) red[tid] += red[tid + off];
        __syncthreads();
    }
    if (tid == 0) g_partial[b] = red[0];
}

// ---------------------------------------------------------------------------
// Stage 3: fold 16 batch partials into the scalar output (deterministic).
// ---------------------------------------------------------------------------
__global__ void knn_stage3(float* __restrict__ out) {
    float s = 0.0f;
#pragma unroll
    for (int b = 0; b < BB; b++) s += g_partial[b];
    out[0] = s * (1.0f / ((float)BB * (float)NN));
}

extern "C" void kernel_launch(void* const* d_in, const int* in_sizes, int n_in,
                              void* d_out, int out_size) {
    const float* pcs = (const float*)d_in[0];
    (void)in_sizes; (void)n_in; (void)out_size;

    dim3 grid1(NN / TPB, BB);
    knn_stage1<<<grid1, TPB>>>(pcs);
    knn_stage2<<<BB, 256>>>();
    knn_stage3<<<1, 1>>>((float*)d_out);
}